// round 8
// baseline (speedup 1.0000x reference)
#include <cuda_runtime.h>
#include <cuda_bf16.h>
#include <stdint.h>

// OptimizerNetwork: 2-layer LSTM-cell meta-optimizer, N=1e6 rows, H=20.
// R7 (HMMA m16n8k16 bf16 hi/lo x3 passes): 163us, L1 66% from ~420 scalar
// LDS per warp-slab. R8: fragment-ordered smem so A frags load as LDS.128
// and B frags as LDS.64; pass loop reuses Ah and Bh; pad cols never restaged
// (zero B columns make stale A harmless). ~120 wide LDS/slab.

#define TPB 128
typedef unsigned uns;

// ---- smem layout (bytes) ----
// A frags: [warp][split][mtile][kstep(cap3)][lane][16B]; mtile stride padded
#define A_MT      1552u     // 3*32*16 + 16 pad
#define A_SPLIT   3104u
#define A_WARP    6208u
#define A_OFF     0u        // 4 warps -> 24832
// B frags: [cell][split][ntile*3+kstep][lane][8B]
#define B1_OFF    24832u
#define B2_OFF    40192u
#define B_SPLIT   7680u     // 10*3*256
#define WOUT_OFF  55552u
#define BOUT_OFF  55632u
#define SMEM_BYTES 55680u

__device__ __forceinline__ float tanha(float x) {
    float r; asm("tanh.approx.f32 %0, %1;" : "=f"(r) : "f"(x)); return r;
}
__device__ __forceinline__ float sigm(float x) {
    return fmaf(0.5f, tanha(0.5f * x), 0.5f);
}

// ---- staging: A pair (cols c,c+1; c even) in fragment order, hi+lo splits ----
__device__ __forceinline__ void stA2(char* wb, int row, int col, float va, float vb) {
    const int mt = row >> 4, mm = row & 15, ks = col >> 4, kk = col & 15;
    const int lane = (mm & 7) * 4 + ((kk & 7) >> 1);
    const int reg = (mm >> 3) + ((kk >> 3) << 1);
    char* p = wb + mt * A_MT + ks * 512 + lane * 16 + reg * 4;
    __nv_bfloat16 ah = __float2bfloat16(va), bh = __float2bfloat16(vb);
    __nv_bfloat162 hv; hv.x = ah; hv.y = bh;
    __nv_bfloat162 lv;
    lv.x = __float2bfloat16(va - __bfloat162float(ah));
    lv.y = __float2bfloat16(vb - __bfloat162float(bh));
    *(__nv_bfloat162*)p = hv;
    *(__nv_bfloat162*)(p + A_SPLIT) = lv;
}
// single A element
__device__ __forceinline__ void stA1(char* wb, int row, int col, float v) {
    const int mt = row >> 4, mm = row & 15, ks = col >> 4, kk = col & 15;
    const int lane = (mm & 7) * 4 + ((kk & 7) >> 1);
    const int reg = (mm >> 3) + ((kk >> 3) << 1);
    char* p = wb + mt * A_MT + ks * 512 + lane * 16 + reg * 4 + (kk & 1) * 2;
    __nv_bfloat16 h = __float2bfloat16(v);
    *(__nv_bfloat16*)p = h;
    *(__nv_bfloat16*)(p + A_SPLIT) = __float2bfloat16(v - __bfloat162float(h));
}
// single B element (prologue only)
__device__ __forceinline__ void stB1(char* cb, int n, int k, float v) {
    const int nt = n >> 3, ks = k >> 4, kk = k & 15;
    const int lane = (n & 7) * 4 + ((kk & 7) >> 1);
    const int reg = kk >> 3;
    char* p = cb + (nt * 3 + ks) * 256 + lane * 8 + reg * 4 + (kk & 1) * 2;
    __nv_bfloat16 h = __float2bfloat16(v);
    *(__nv_bfloat16*)p = h;
    *(__nv_bfloat16*)(p + B_SPLIT) = __float2bfloat16(v - __bfloat162float(h));
}

__device__ __forceinline__ void mma16816(float* c, const uns* a, const uns* b) {
    asm volatile("mma.sync.aligned.m16n8k16.row.col.f32.bf16.bf16.f32 "
        "{%0,%1,%2,%3}, {%4,%5,%6,%7}, {%8,%9}, {%0,%1,%2,%3};"
        : "+f"(c[0]), "+f"(c[1]), "+f"(c[2]), "+f"(c[3])
        : "r"(a[0]), "r"(a[1]), "r"(a[2]), "r"(a[3]), "r"(b[0]), "r"(b[1]));
}

// gates GEMM: C = (Ah+Al)(Bh+Bl) minus AlBl (~2^-16). A frags via LDS.128,
// B frags via LDS.64; Ah reused for 2 passes, Bh for 2 passes.
template <int KS>
__device__ __forceinline__ void gemm(float C[10][2][4], const char* wb,
                                     const char* bbase, int l) {
#pragma unroll
    for (int n = 0; n < 10; ++n)
#pragma unroll
        for (int m = 0; m < 2; ++m)
#pragma unroll
            for (int q = 0; q < 4; ++q) C[n][m][q] = 0.f;
#pragma unroll
    for (int ks = 0; ks < KS; ++ks) {
        uint4 ah0 = *(const uint4*)(wb + ks * 512 + l * 16);
        uint4 ah1 = *(const uint4*)(wb + A_MT + ks * 512 + l * 16);
        uint4 al0 = *(const uint4*)(wb + A_SPLIT + ks * 512 + l * 16);
        uint4 al1 = *(const uint4*)(wb + A_SPLIT + A_MT + ks * 512 + l * 16);
        uint2 b[10];
#pragma unroll
        for (int n = 0; n < 10; ++n)
            b[n] = *(const uint2*)(bbase + (n * 3 + ks) * 256 + l * 8);
#pragma unroll
        for (int n = 0; n < 10; ++n) {
            mma16816(C[n][0], (const uns*)&ah0, (const uns*)&b[n]);
            mma16816(C[n][1], (const uns*)&ah1, (const uns*)&b[n]);
        }
#pragma unroll
        for (int n = 0; n < 10; ++n) {
            mma16816(C[n][0], (const uns*)&al0, (const uns*)&b[n]);
            mma16816(C[n][1], (const uns*)&al1, (const uns*)&b[n]);
        }
#pragma unroll
        for (int n = 0; n < 10; ++n)
            b[n] = *(const uint2*)(bbase + B_SPLIT + (n * 3 + ks) * 256 + l * 8);
#pragma unroll
        for (int n = 0; n < 10; ++n) {
            mma16816(C[n][0], (const uns*)&ah0, (const uns*)&b[n]);
            mma16816(C[n][1], (const uns*)&ah1, (const uns*)&b[n]);
        }
    }
}

__global__ void __launch_bounds__(TPB, 3)
optnet_mma(const float* __restrict__ inp,
           const float* __restrict__ h0g, const float* __restrict__ h1g,
           const float* __restrict__ c0g, const float* __restrict__ c1g,
           const float* __restrict__ Wih1, const float* __restrict__ Whh1,
           const float* __restrict__ bih1, const float* __restrict__ bhh1,
           const float* __restrict__ Wih2, const float* __restrict__ Whh2,
           const float* __restrict__ bih2, const float* __restrict__ bhh2,
           const float* __restrict__ Wout, const float* __restrict__ bout,
           float* __restrict__ out, int N)
{
    extern __shared__ char sm[];
    const int tid = threadIdx.x;
    const int wid = tid >> 5;
    const int l = tid & 31;

    // ---- prologue: zero everything, stage permuted weight frags + consts ----
    for (int i = tid; i < (int)(SMEM_BYTES / 16); i += TPB)
        ((float4*)sm)[i] = make_float4(0.f, 0.f, 0.f, 0.f);
    __syncthreads();

    // B row p: p=2h -> i_h (W row h), 2h+1 -> f_h (20+h),
    //          40+2h -> g_h (40+h), 41+2h -> o_h (60+h)
    if (tid < 80) {
        const int p = tid;
        int h, r;
        if (p < 40) { h = p >> 1; r = (p & 1) ? 20 + h : h; }
        else { int q = p - 40; h = q >> 1; r = (q & 1) ? 60 + h : 40 + h; }
        char* b1 = sm + B1_OFF;
        char* b2 = sm + B2_OFF;
        stB1(b1, p, 0, Wih1[r * 2 + 0]);
        stB1(b1, p, 1, Wih1[r * 2 + 1]);
        for (int k = 0; k < 20; ++k) {
            stB1(b1, p, 2 + k, Whh1[r * 20 + k]);
            stB1(b2, p, k, Wih2[r * 20 + k]);
            stB1(b2, p, 20 + k, Whh2[r * 20 + k]);
        }
        stB1(b1, p, 22, bih1[r] + bhh1[r]);
        stB1(b2, p, 40, bih2[r] + bhh2[r]);
    }
    if (tid < 20) ((float*)(sm + WOUT_OFF))[tid] = Wout[tid];
    if (tid == 0) *(float*)(sm + BOUT_OFF) = bout[0];
    // A bias col 40 (cell2) is never overwritten by per-slab staging: set once.
    {
        char* wb = sm + A_OFF + (uns)(tid >> 5) * A_WARP;
        stA2(wb, tid & 31, 40, 1.f, 0.f);
    }
    __syncthreads();

    float woutR[5];
#pragma unroll
    for (int j = 0; j < 5; ++j)
        woutR[j] = ((const float*)(sm + WOUT_OFF))[(l & 3) + 4 * j];
    const float boutv = *(const float*)(sm + BOUT_OFF);

    // output tuple sections: out, h0n@N, h1n@21N, c0n@41N, c1n@61N
    float* h0n_out = out + (size_t)N;
    float* h1n_out = out + (size_t)N * 21;
    float* c0n_out = out + (size_t)N * 41;
    float* c1n_out = out + (size_t)N * 61;

    char* wb = sm + A_OFF + (uns)wid * A_WARP;
    const char* b1base = sm + B1_OFF;
    const char* b2base = sm + B2_OFF;

    const int nslabs = (N + 31) / 32;
    const int twarps = gridDim.x * 4;
    float C[10][2][4];

    for (int s = blockIdx.x * 4 + wid; s < nslabs; s += twarps) {
        const int rowbase = s * 32;

        // ---- stage A cell1: x_pre (cols 0,1), bias (22), h0 (2..21) ----
        {
            const int grow = rowbase + l;
            float x = (grow < N) ? inp[grow] : 0.f;
            float ax = fabsf(x), pa, pb;
            if (ax >= 4.5399930e-05f) {        // exp(-10)
                pa = __logf(ax + 1e-8f) * 0.1f;
                pb = (x > 0.f) ? 1.f : -1.f;
            } else {
                pa = -1.f;
                pb = 22026.4658f * x;          // exp(10)
            }
            stA2(wb, l, 0, pa, pb);
            stA2(wb, l, 22, 1.f, 0.f);         // bias col (clobbered by h1 later)
#pragma unroll
            for (int q = 0; q < 5; ++q) {
                const int idx = q * 32 + l;          // float4 id in slab
                const int gr = idx / 5, cp = idx % 5;
                float4 v = make_float4(0.f, 0.f, 0.f, 0.f);
                if (rowbase + gr < N)
                    v = ((const float4*)(h0g + (size_t)rowbase * 20))[idx];
                stA2(wb, gr, 2 + cp * 4, v.x, v.y);
                stA2(wb, gr, 4 + cp * 4, v.z, v.w);
            }
        }
        __syncwarp();

        // ---- cell1 GEMM: K=32 (cols 23..31 stale-but-finite x B=0) ----
        gemm<2>(C, wb, b1base, l);
        __syncwarp();

        // ---- epilogue 1 + stage h0n (A cols 0..19) ----
#pragma unroll
        for (int rs = 0; rs < 4; ++rs) {
            const int mt = rs >> 1, cb = (rs & 1) * 2;
            const int rloc = (l >> 2) + 8 * rs;
            const size_t grow = (size_t)rowbase + rloc;
            const bool ok = grow < (size_t)N;
#pragma unroll
            for (int j = 0; j < 5; ++j) {
                const int h = (l & 3) + 4 * j;
                float I = sigm(C[j][mt][cb]);
                float F = sigm(C[j][mt][cb + 1]);
                float G = tanha(C[j + 5][mt][cb]);
                float O = sigm(C[j + 5][mt][cb + 1]);
                float cin = ok ? c0g[grow * 20 + h] : 0.f;
                float cn = fmaf(F, cin, I * G);
                float hn = O * tanha(cn);
                if (ok) {
                    c0n_out[grow * 20 + h] = cn;
                    h0n_out[grow * 20 + h] = hn;
                }
                stA1(wb, rloc, h, hn);
            }
        }
        // stage h1 (cols 20..39); bias col 40 persists from prologue
        {
#pragma unroll
            for (int q = 0; q < 5; ++q) {
                const int idx = q * 32 + l;
                const int gr = idx / 5, cp = idx % 5;
                float4 v = make_float4(0.f, 0.f, 0.f, 0.f);
                if (rowbase + gr < N)
                    v = ((const float4*)(h1g + (size_t)rowbase * 20))[idx];
                stA2(wb, gr, 20 + cp * 4, v.x, v.y);
                stA2(wb, gr, 22 + cp * 4, v.z, v.w);
            }
        }
        __syncwarp();

        // ---- cell2 GEMM: K=48 (cols 41..47 zero) ----
        gemm<3>(C, wb, b2base, l);

        // ---- epilogue 2: c1n, h1n, out = h1n.Wout + bout ----
#pragma unroll
        for (int rs = 0; rs < 4; ++rs) {
            const int mt = rs >> 1, cb = (rs & 1) * 2;
            const int rloc = (l >> 2) + 8 * rs;
            const size_t grow = (size_t)rowbase + rloc;
            const bool ok = grow < (size_t)N;
            float psum = 0.f;
#pragma unroll
            for (int j = 0; j < 5; ++j) {
                const int h = (l & 3) + 4 * j;
                float I = sigm(C[j][mt][cb]);
                float F = sigm(C[j][mt][cb + 1]);
                float G = tanha(C[j + 5][mt][cb]);
                float O = sigm(C[j + 5][mt][cb + 1]);
                float cin = ok ? c1g[grow * 20 + h] : 0.f;
                float cn = fmaf(F, cin, I * G);
                float hn = O * tanha(cn);
                if (ok) {
                    c1n_out[grow * 20 + h] = cn;
                    h1n_out[grow * 20 + h] = hn;
                }
                psum = fmaf(hn, woutR[j], psum);
            }
            psum += __shfl_xor_sync(0xFFFFFFFFu, psum, 1);
            psum += __shfl_xor_sync(0xFFFFFFFFu, psum, 2);
            if (ok && (l & 3) == 0) out[grow] = psum + boutv;
        }
        __syncwarp();   // before next iteration restages A
    }
}

extern "C" void kernel_launch(void* const* d_in, const int* in_sizes, int n_in,
                              void* d_out, int out_size)
{
    static int configured = 0;
    if (!configured) {
        cudaFuncSetAttribute(optnet_mma,
                             cudaFuncAttributeMaxDynamicSharedMemorySize,
                             SMEM_BYTES);
        configured = 1;
    }
    const int N = in_sizes[0];
    const int grid = 444;   // 3 CTAs/SM x 148 SMs, persistent
    optnet_mma<<<grid, TPB, SMEM_BYTES>>>(
        (const float*)d_in[0], (const float*)d_in[1], (const float*)d_in[2],
        (const float*)d_in[3], (const float*)d_in[4],
        (const float*)d_in[5], (const float*)d_in[6],
        (const float*)d_in[7], (const float*)d_in[8],
        (const float*)d_in[9], (const float*)d_in[10],
        (const float*)d_in[11], (const float*)d_in[12],
        (const float*)d_in[13], (const float*)d_in[14],
        (float*)d_out, N);
}